// round 7
// baseline (speedup 1.0000x reference)
#include <cuda_runtime.h>
#include <cuda_bf16.h>
#include <cstdint>

// ---------------- problem-size scratch (static __device__, no allocs) --------
#define N_MAX 100000
#define N_PAD (N_MAX + 128)
#define E_MAX 1600000

__device__ float g_bufA[(size_t)N_MAX * 128];   // fp32 GEMM output (128 cols)
__device__ float g_bufC[(size_t)N_MAX * 64];    // fp32 GEMM output (64 cols)
__device__ unsigned g_Xh[(size_t)N_PAD * 64];   // bf16x2 hi pairs (padded rows)
__device__ unsigned g_Xl[(size_t)N_PAD * 64];
__device__ unsigned g_Hh[(size_t)N_PAD * 64];
__device__ unsigned g_Hl[(size_t)N_PAD * 64];
__device__ float g_dinv[N_MAX];
__device__ int   g_cnt[N_MAX];
__device__ int   g_off[N_MAX + 1];
__device__ int   g_cur[N_MAX];
__device__ int   g_srcs[E_MAX];
__device__ float g_wn[E_MAX];
__device__ int   g_bsum[256];
__device__ int   g_bexc[256];
__device__ int   g_is64;

// W^T as bf16 hi/lo pairs: layout [n][kpair], i.e. n*64 + kp.
__device__ unsigned g_Bh0[128 * 64];
__device__ unsigned g_Bl0[128 * 64];
__device__ unsigned g_Bh1[128 * 64];
__device__ unsigned g_Bl1[128 * 64];
__device__ unsigned g_Bh2[64 * 64];
__device__ unsigned g_Bl2[64 * 64];

// ---------------- misc helpers -----------------------------------------------
__device__ __forceinline__ int edge_at(const void* p, long long idx) {
    if (g_is64) return (int)((const long long*)p)[idx];
    return ((const int*)p)[idx];
}

__device__ __forceinline__ uint32_t smem_u32(const void* p) {
    uint32_t a;
    asm("{ .reg .u64 t; cvta.to.shared.u64 t, %1; cvt.u32.u64 %0, t; }"
        : "=r"(a) : "l"(p));
    return a;
}

__device__ __forceinline__ void split2(float x, float y, unsigned& hi,
                                       unsigned& lo) {
    __nv_bfloat16 h0 = __float2bfloat16_rn(x);
    __nv_bfloat16 h1 = __float2bfloat16_rn(y);
    __nv_bfloat16 l0 = __float2bfloat16_rn(x - __bfloat162float(h0));
    __nv_bfloat16 l1 = __float2bfloat16_rn(y - __bfloat162float(h1));
    __nv_bfloat162 hp = __nv_bfloat162(h0, h1);
    __nv_bfloat162 lp = __nv_bfloat162(l0, l1);
    hi = *(unsigned*)&hp;
    lo = *(unsigned*)&lp;
}

// detect int64 vs int32 edges, and zero g_cnt (fused)
__global__ void detect_init_k(const unsigned int* __restrict__ p, int e,
                              int n) {
    int i = blockIdx.x * blockDim.x + threadIdx.x;
    if (i < n) g_cnt[i] = 0;
    if (blockIdx.x == 0) {
        __shared__ int any;
        if (threadIdx.x == 0) any = 0;
        __syncthreads();
        int lim = e < 8192 ? e : 8192;
        for (int j = threadIdx.x; j < lim; j += blockDim.x)
            if (p[2 * j + 1] != 0u) any = 1;
        __syncthreads();
        if (threadIdx.x == 0) g_is64 = any ? 0 : 1;
    }
}

// ---------------- X split: fp32 [n][128] -> bf16 hi/lo pairs [n][64] ---------
__global__ void xsplit_k(const float2* __restrict__ X,
                         unsigned* __restrict__ Hh, unsigned* __restrict__ Hl,
                         int total) {
    int idx = blockIdx.x * blockDim.x + threadIdx.x;
    if (idx >= total) return;
    float2 f = X[idx];
    split2(f.x, f.y, Hh[idx], Hl[idx]);
}

// ---------------- CSR build --------------------------------------------------
__global__ void count_k(const void* __restrict__ edges, int E) {
    int i = blockIdx.x * blockDim.x + threadIdx.x;
    if (i < E) {
        int tgt = edge_at(edges, (long long)E + i);
        atomicAdd(&g_cnt[tgt], 1);
    }
}

__global__ void scan_part_k(int n) {
    __shared__ int sh[1024];
    int t = threadIdx.x;
    int i = blockIdx.x * 1024 + t;
    int v = (i < n) ? g_cnt[i] : 0;
    if (i < n) g_dinv[i] = rsqrtf((float)(v + 1));
    int val = v;
    sh[t] = val;
    __syncthreads();
#pragma unroll
    for (int d = 1; d < 1024; d <<= 1) {
        int y = (t >= d) ? sh[t - d] : 0;
        __syncthreads();
        val += y;
        sh[t] = val;
        __syncthreads();
    }
    if (i < n) g_off[i] = val - v;
    if (t == 1023) g_bsum[blockIdx.x] = val;
}

__global__ void scan_bsum_k(int nb) {
    if (threadIdx.x == 0 && blockIdx.x == 0) {
        int run = 0;
        for (int i = 0; i < nb; i++) { g_bexc[i] = run; run += g_bsum[i]; }
    }
}

__global__ void scan_add_k(int n, int E) {
    int i = blockIdx.x * blockDim.x + threadIdx.x;
    if (i < n) {
        g_off[i] += g_bexc[i >> 10];
        g_cur[i] = 0;
    }
    if (i == 0) g_off[n] = E;
}

__global__ void fill_k(const void* __restrict__ edges, int E) {
    int i = blockIdx.x * blockDim.x + threadIdx.x;
    if (i < E) {
        int src = edge_at(edges, i);
        int tgt = edge_at(edges, (long long)E + i);
        int pos = g_off[tgt] + atomicAdd(&g_cur[tgt], 1);
        g_srcs[pos] = src;
        g_wn[pos] = g_dinv[src] * g_dinv[tgt];
    }
}

// ---------------- W preprocessing: all three W -> WT bf16 hi/lo pairs --------
__global__ void wprep_all_k(const float* __restrict__ W0,
                            const float* __restrict__ W1,
                            const float* __restrict__ W2,
                            unsigned* __restrict__ Bh0, unsigned* __restrict__ Bl0,
                            unsigned* __restrict__ Bh1, unsigned* __restrict__ Bl1,
                            unsigned* __restrict__ Bh2, unsigned* __restrict__ Bl2) {
    int gid = blockIdx.x * blockDim.x + threadIdx.x;
    const float* Wg;
    unsigned *Bh, *Bl;
    int idx, N;
    if (gid < 128 * 64) {
        Wg = W0; Bh = Bh0; Bl = Bl0; idx = gid; N = 128;
    } else if (gid < 2 * 128 * 64) {
        Wg = W1; Bh = Bh1; Bl = Bl1; idx = gid - 128 * 64; N = 128;
    } else if (gid < 2 * 128 * 64 + 64 * 64) {
        Wg = W2; Bh = Bh2; Bl = Bl2; idx = gid - 2 * 128 * 64; N = 64;
    } else {
        return;
    }
    int n = idx >> 6;
    int kp = idx & 63;
    int k = 2 * kp;
    split2(Wg[(size_t)k * N + n], Wg[(size_t)(k + 1) * N + n], Bh[idx], Bl[idx]);
}

// ---------------- HMMA GEMM: Y[:,cb:cb+64] = X[64 rows,128] @ W -------------
// 3-term bf16 split via mma.sync.m16n8k16, cp.async K-split pipeline,
// M64 x N64 tile, 3 CTAs/SM for latency overlap.
#define CST 36
#define OFF_A(c, t) (((c) * 2 + (t)) * 64 * CST)
#define OFF_B(c, t) (4 * 64 * CST + ((c) * 2 + (t)) * 64 * CST)
#define GEMM_SMEM (8 * 64 * CST * 4)  // 73728 B

__device__ __forceinline__ void mma16816(float* c, const unsigned* a,
                                         const unsigned* b) {
    asm volatile(
        "mma.sync.aligned.m16n8k16.row.col.f32.bf16.bf16.f32 "
        "{%0,%1,%2,%3}, {%4,%5,%6,%7}, {%8,%9}, {%0,%1,%2,%3};"
        : "+f"(c[0]), "+f"(c[1]), "+f"(c[2]), "+f"(c[3])
        : "r"(a[0]), "r"(a[1]), "r"(a[2]), "r"(a[3]), "r"(b[0]), "r"(b[1]));
}

#define LDSM4(r, addr) \
    asm volatile( \
        "ldmatrix.sync.aligned.m8n8.x4.shared.b16 {%0,%1,%2,%3}, [%4];" \
        : "=r"((r)[0]), "=r"((r)[1]), "=r"((r)[2]), "=r"((r)[3]) \
        : "r"(addr))

#define CP16(dst, src) \
    asm volatile("cp.async.cg.shared.global [%0], [%1], 16;" :: "r"(dst), \
                 "l"(src))
#define CP_COMMIT() asm volatile("cp.async.commit_group;" ::: "memory")
#define CP_WAIT1() asm volatile("cp.async.wait_group 1;" ::: "memory")
#define CP_WAIT0() asm volatile("cp.async.wait_group 0;" ::: "memory")

__global__ __launch_bounds__(256, 3) void mma_gemm_k(
    const unsigned* __restrict__ Xh, const unsigned* __restrict__ Xl,
    const unsigned* __restrict__ gBh, const unsigned* __restrict__ gBl,
    float* __restrict__ Y, int nrows, int NOUT) {
    extern __shared__ unsigned sm[];
    const uint32_t sb = smem_u32(sm);
    const int tid = threadIdx.x;
    const int wid = tid >> 5;
    const int l = tid & 31;
    const int row0 = blockIdx.x * 64;
    const int cb = blockIdx.y * 64;

    // async loads, one commit group per K-chunk (A rows unconditional: padded)
#pragma unroll
    for (int c = 0; c < 2; c++) {
#pragma unroll
        for (int i = tid; i < 64 * 8; i += 256) {
            int m = i >> 3, c4 = i & 7;
            size_t gA = (size_t)(row0 + m) * 64 + c * 32 + c4 * 4;
            size_t gB = (size_t)(cb + m) * 64 + c * 32 + c4 * 4;
            CP16(sb + (OFF_A(c, 0) + m * CST + c4 * 4) * 4, Xh + gA);
            CP16(sb + (OFF_A(c, 1) + m * CST + c4 * 4) * 4, Xl + gA);
            CP16(sb + (OFF_B(c, 0) + m * CST + c4 * 4) * 4, gBh + gB);
            CP16(sb + (OFF_B(c, 1) + m * CST + c4 * 4) * 4, gBl + gB);
        }
        CP_COMMIT();
    }

    const int wm = wid & 1;   // rows 32*wm .. +32
    const int wn = wid >> 1;  // cols 16*wn .. +16
    const int lr = l >> 2;
    const int lq = l & 3;

    const uint32_t aoff =
        (((l & 7) + ((l >> 3) & 1) * 8 + wm * 32) * CST + (l >> 4) * 4) * 4;
    const uint32_t boff =
        ((wn * 16 + ((l >> 4) & 1) * 8 + (l & 7)) * CST + ((l >> 3) & 1) * 4) * 4;

    float acc[2][2][4];
#pragma unroll
    for (int mt = 0; mt < 2; mt++)
#pragma unroll
        for (int nt = 0; nt < 2; nt++)
#pragma unroll
            for (int p = 0; p < 4; p++) acc[mt][nt][p] = 0.f;

#pragma unroll
    for (int c = 0; c < 2; c++) {
        if (c == 0) CP_WAIT1(); else CP_WAIT0();
        __syncthreads();
#pragma unroll
        for (int term = 0; term < 3; term++) {
            const uint32_t aA = sb + OFF_A(c, term == 2 ? 1 : 0) * 4 + aoff;
            const uint32_t bB = sb + OFF_B(c, term == 1 ? 1 : 0) * 4 + boff;
#pragma unroll
            for (int ks = 0; ks < 4; ks++) {
                unsigned a[2][4], t0[4];
                LDSM4(a[0], aA + ks * 32);
                LDSM4(a[1], aA + ks * 32 + 16 * CST * 4);
                LDSM4(t0, bB + ks * 32);
                unsigned b[2][2] = {{t0[0], t0[1]}, {t0[2], t0[3]}};
#pragma unroll
                for (int mt = 0; mt < 2; mt++)
#pragma unroll
                    for (int nt = 0; nt < 2; nt++)
                        mma16816(acc[mt][nt], a[mt], b[nt]);
            }
        }
    }

    // epilogue
#pragma unroll
    for (int mt = 0; mt < 2; mt++) {
        int r = row0 + wm * 32 + mt * 16 + lr;
        int r2 = r + 8;
#pragma unroll
        for (int nt = 0; nt < 2; nt++) {
            int cc = cb + wn * 16 + nt * 8 + lq * 2;
            if (r < nrows) {
                float2* y = (float2*)(Y + (size_t)r * NOUT + cc);
                *y = make_float2(acc[mt][nt][0], acc[mt][nt][1]);
            }
            if (r2 < nrows) {
                float2* y = (float2*)(Y + (size_t)r2 * NOUT + cc);
                *y = make_float2(acc[mt][nt][2], acc[mt][nt][3]);
            }
        }
    }
}

// ---------------- aggregation (8-wide gather unroll for MLP) ------------------
template <int F, bool RELU, bool SPLIT>
__global__ __launch_bounds__(256) void agg_k(const float4* __restrict__ H,
                                             const float* __restrict__ bias,
                                             float* __restrict__ out,
                                             unsigned* __restrict__ outH,
                                             unsigned* __restrict__ outL,
                                             int n) {
    constexpr int LPN = F / 4;
    constexpr int NPW = 32 / LPN;
    int gt = blockIdx.x * blockDim.x + threadIdx.x;
    int warp = gt >> 5;
    int lane = gt & 31;
    int sub = lane / LPN;
    int ln = lane % LPN;
    int v = warp * NPW + sub;
    bool valid = v < n;
    if (v >= n) v = n - 1;

    float4 acc = ((const float4*)bias)[ln];
    float dv = g_dinv[v];
    float w0 = dv * dv;
    float4 hv = H[(size_t)v * LPN + ln];
    acc.x += w0 * hv.x; acc.y += w0 * hv.y;
    acc.z += w0 * hv.z; acc.w += w0 * hv.w;

    int s = g_off[v], eend = g_off[v + 1];
    for (int i = s; i < eend; i += LPN) {
        int j = i + ln;
        int src = 0;
        float w = 0.f;
        if (j < eend) { src = g_srcs[j]; w = g_wn[j]; }
        int cnt = eend - i;
        if (cnt > LPN) cnt = LPN;
        int t = 0;
        for (; t + 8 <= cnt; t += 8) {
            int ss[8];
            float ww[8];
            float4 hh[8];
#pragma unroll
            for (int u = 0; u < 8; u++) {
                ss[u] = __shfl_sync(0xffffffffu, src, t + u, LPN);
                ww[u] = __shfl_sync(0xffffffffu, w, t + u, LPN);
            }
#pragma unroll
            for (int u = 0; u < 8; u++) hh[u] = H[(size_t)ss[u] * LPN + ln];
#pragma unroll
            for (int u = 0; u < 8; u++) {
                acc.x += ww[u] * hh[u].x; acc.y += ww[u] * hh[u].y;
                acc.z += ww[u] * hh[u].z; acc.w += ww[u] * hh[u].w;
            }
        }
        for (; t + 4 <= cnt; t += 4) {
            int ss[4];
            float ww[4];
            float4 hh[4];
#pragma unroll
            for (int u = 0; u < 4; u++) {
                ss[u] = __shfl_sync(0xffffffffu, src, t + u, LPN);
                ww[u] = __shfl_sync(0xffffffffu, w, t + u, LPN);
            }
#pragma unroll
            for (int u = 0; u < 4; u++) hh[u] = H[(size_t)ss[u] * LPN + ln];
#pragma unroll
            for (int u = 0; u < 4; u++) {
                acc.x += ww[u] * hh[u].x; acc.y += ww[u] * hh[u].y;
                acc.z += ww[u] * hh[u].z; acc.w += ww[u] * hh[u].w;
            }
        }
        for (; t < cnt; t++) {
            int st = __shfl_sync(0xffffffffu, src, t, LPN);
            float wt = __shfl_sync(0xffffffffu, w, t, LPN);
            float4 h = H[(size_t)st * LPN + ln];
            acc.x += wt * h.x; acc.y += wt * h.y;
            acc.z += wt * h.z; acc.w += wt * h.w;
        }
    }

    if (RELU) {
        acc.x = fmaxf(acc.x, 0.f); acc.y = fmaxf(acc.y, 0.f);
        acc.z = fmaxf(acc.z, 0.f); acc.w = fmaxf(acc.w, 0.f);
    }
    if (!valid) return;
    if (SPLIT) {
        unsigned h0, l0, h1, l1;
        split2(acc.x, acc.y, h0, l0);
        split2(acc.z, acc.w, h1, l1);
        ((uint2*)outH)[(size_t)v * (F / 4) + ln] = make_uint2(h0, h1);
        ((uint2*)outL)[(size_t)v * (F / 4) + ln] = make_uint2(l0, l1);
    } else {
        ((float4*)out)[(size_t)v * LPN + ln] = acc;
    }
}

// ---------------- launch ------------------------------------------------------
extern "C" void kernel_launch(void* const* d_in, const int* in_sizes, int n_in,
                              void* d_out, int out_size) {
    const float* x = (const float*)d_in[0];
    const void* edges = d_in[1];
    const float* W0 = (const float*)d_in[2];
    const float* b0 = (const float*)d_in[3];
    const float* W1 = (const float*)d_in[4];
    const float* b1 = (const float*)d_in[5];
    const float* W2 = (const float*)d_in[6];
    const float* b2 = (const float*)d_in[7];

    int n = in_sizes[0] / 128;
    int E = in_sizes[1] / 2;
    if (n > N_MAX) n = N_MAX;
    if (E > E_MAX) E = E_MAX;

    void *pA, *pC, *pXh, *pXl, *pHh, *pHl;
    cudaGetSymbolAddress(&pA, g_bufA);
    cudaGetSymbolAddress(&pC, g_bufC);
    cudaGetSymbolAddress(&pXh, g_Xh);
    cudaGetSymbolAddress(&pXl, g_Xl);
    cudaGetSymbolAddress(&pHh, g_Hh);
    cudaGetSymbolAddress(&pHl, g_Hl);
    float* bufA = (float*)pA;
    float* bufC = (float*)pC;
    unsigned* Xh = (unsigned*)pXh;
    unsigned* Xl = (unsigned*)pXl;
    unsigned* Hh = (unsigned*)pHh;
    unsigned* Hl = (unsigned*)pHl;

    void *ph0, *pl0, *ph1, *pl1, *ph2, *pl2;
    cudaGetSymbolAddress(&ph0, g_Bh0);
    cudaGetSymbolAddress(&pl0, g_Bl0);
    cudaGetSymbolAddress(&ph1, g_Bh1);
    cudaGetSymbolAddress(&pl1, g_Bl1);
    cudaGetSymbolAddress(&ph2, g_Bh2);
    cudaGetSymbolAddress(&pl2, g_Bl2);

    cudaFuncSetAttribute(mma_gemm_k,
                         cudaFuncAttributeMaxDynamicSharedMemorySize, GEMM_SMEM);

    // side stream + events, created once on the first (uncaptured) call
    static cudaStream_t s2 = nullptr;
    static cudaEvent_t e1 = nullptr, e2 = nullptr;
    static bool fork_ok = false;
    if (!s2) {
        fork_ok =
            (cudaStreamCreateWithFlags(&s2, cudaStreamNonBlocking) == cudaSuccess) &&
            (cudaEventCreateWithFlags(&e1, cudaEventDisableTiming) == cudaSuccess) &&
            (cudaEventCreateWithFlags(&e2, cudaEventDisableTiming) == cudaSuccess);
        if (!fork_ok) s2 = (cudaStream_t)0;
    }
    cudaStream_t sc = fork_ok ? s2 : (cudaStream_t)0;  // CSR-branch stream

    int nb256 = (n + 255) / 256;
    int eb256 = (E + 255) / 256;
    int nb = (n + 1023) / 1024;
    int ntiles = (n + 63) / 64;
    dim3 g128(ntiles, 2);
    dim3 g64(ntiles, 1);

    // main branch: detect -> xsplit -> wprep -> gemm1
    detect_init_k<<<nb256, 256>>>((const unsigned int*)edges, E, n);
    if (fork_ok) {
        cudaEventRecord(e1, 0);
        cudaStreamWaitEvent(sc, e1, 0);
    }
    xsplit_k<<<(n * 64 + 255) / 256, 256>>>((const float2*)x, Xh, Xl, n * 64);
    wprep_all_k<<<(2 * 128 * 64 + 64 * 64 + 255) / 256, 256>>>(
        W0, W1, W2, (unsigned*)ph0, (unsigned*)pl0, (unsigned*)ph1,
        (unsigned*)pl1, (unsigned*)ph2, (unsigned*)pl2);
    mma_gemm_k<<<g128, 256, GEMM_SMEM>>>(Xh, Xl, (const unsigned*)ph0,
                                         (const unsigned*)pl0, bufA, n, 128);

    // CSR branch (overlaps main branch)
    count_k<<<eb256, 256, 0, sc>>>(edges, E);
    scan_part_k<<<nb, 1024, 0, sc>>>(n);
    scan_bsum_k<<<1, 32, 0, sc>>>(nb);
    scan_add_k<<<nb256, 256, 0, sc>>>(n, E);
    fill_k<<<eb256, 256, 0, sc>>>(edges, E);
    if (fork_ok) {
        cudaEventRecord(e2, sc);
        cudaStreamWaitEvent((cudaStream_t)0, e2, 0);
    }

    // layer 1 agg -> split bf16
    agg_k<128, true, true><<<(n * 32 + 255) / 256, 256>>>(
        (const float4*)bufA, b0, nullptr, Hh, Hl, n);
    // layer 2
    mma_gemm_k<<<g128, 256, GEMM_SMEM>>>(Hh, Hl, (const unsigned*)ph1,
                                         (const unsigned*)pl1, bufA, n, 128);
    agg_k<128, true, true><<<(n * 32 + 255) / 256, 256>>>(
        (const float4*)bufA, b1, nullptr, Xh, Xl, n);
    // layer 3
    mma_gemm_k<<<g64, 256, GEMM_SMEM>>>(Xh, Xl, (const unsigned*)ph2,
                                        (const unsigned*)pl2, bufC, n, 64);
    agg_k<64, false, false><<<(n * 16 + 255) / 256, 256>>>(
        (const float4*)bufC, b2, (float*)d_out, nullptr, nullptr, n);
}